// round 9
// baseline (speedup 1.0000x reference)
#include <cuda_runtime.h>
#include <cuda_bf16.h>
#include <cuda_fp16.h>
#include <mma.h>
#include <cstdint>

using namespace nvcuda;

#define DIM_IN  128
#define DIM_HID 256
#define DIM_OUT 128
#define NEXP    8
#define MAXN    65536
#define MAXROWS (2 * MAXN)
#define MAXTILES (MAXROWS / 128 + NEXP)

#if defined(__CUDA_ARCH__) && (defined(__CUDA_ARCH_FEAT_SM103_ALL) || defined(__CUDA_ARCH_FEAT_SM100_ALL))
#define HAS_TCGEN05 1
#else
#define HAS_TCGEN05 0
#endif

// ---------------- device scratch ----------------
__device__ int    g_counts[NEXP];
__device__ int    g_cursor[NEXP];
__device__ int    g_numTiles;
__device__ int    g_tileExpert[MAXTILES];
__device__ int    g_tileStart[MAXTILES];
__device__ int    g_tileRows[MAXTILES];
__device__ int    g_tokE[MAXN];
__device__ float2 g_tokW[MAXN];
__device__ int    g_rowToken[MAXROWS];
__device__ float  g_rowW[MAXROWS];

// bf16 hi/lo (tcgen05 path; weights transposed)
__device__ __align__(16) __nv_bfloat16 g_xbhi[MAXN * DIM_IN];
__device__ __align__(16) __nv_bfloat16 g_xblo[MAXN * DIM_IN];
__device__ __align__(16) __nv_bfloat16 g_w1thi[NEXP * DIM_HID * DIM_IN];  // [e][n=256][k=128]
__device__ __align__(16) __nv_bfloat16 g_w1tlo[NEXP * DIM_HID * DIM_IN];
__device__ __align__(16) __nv_bfloat16 g_w2thi[NEXP * DIM_OUT * DIM_HID]; // [e][n=128][k=256]
__device__ __align__(16) __nv_bfloat16 g_w2tlo[NEXP * DIM_OUT * DIM_HID];
// fp16 (WMMA fallback; original layout)
__device__ __align__(16) __half g_xfhi[MAXN * DIM_IN];
__device__ __align__(16) __half g_xflo[MAXN * DIM_IN];
__device__ __align__(16) __half g_w1f[NEXP * DIM_IN * DIM_HID];  // [e][k][n]
__device__ __align__(16) __half g_w2f[NEXP * DIM_HID * DIM_OUT];

// ---------------- kernel: weight prep (transpose+bf16 split, fp16 copy) ----------------
__global__ void __launch_bounds__(256) moe_prep(
    const float* __restrict__ W1, const float* __restrict__ W2)
{
    __shared__ float ts[32][33];
    int b = blockIdx.x;
    int tx = threadIdx.x & 31, ty = threadIdx.x >> 5;   // 32x8

    if (b == 0 && threadIdx.x < NEXP) g_counts[threadIdx.x] = 0;

    if (b < 256) {                                       // W1: [e][128k][256n]
        int e = b >> 5, t = b & 31;
        int kt = t >> 3, nt = t & 7;
        const float* src = W1 + (long)e * 128 * 256;
        #pragma unroll
        for (int r = 0; r < 32; r += 8) {
            long si = (long)(kt * 32 + ty + r) * 256 + nt * 32 + tx;
            float v = src[si];
            ts[ty + r][tx] = v;
            g_w1f[(long)e * 128 * 256 + si] = __float2half_rn(v);
        }
        __syncthreads();
        #pragma unroll
        for (int r = 0; r < 32; r += 8) {
            float v = ts[tx][ty + r];
            __nv_bfloat16 hi = __float2bfloat16_rn(v);
            __nv_bfloat16 lo = __float2bfloat16_rn(v - __bfloat162float(hi));
            long o = (long)e * 256 * 128 + (long)(nt * 32 + ty + r) * 128 + kt * 32 + tx;
            g_w1thi[o] = hi; g_w1tlo[o] = lo;
        }
    } else {                                             // W2: [e][256k][128n]
        int bb = b - 256;
        int e = bb >> 5, t = bb & 31;
        int kt = t >> 2, nt = t & 3;
        const float* src = W2 + (long)e * 256 * 128;
        #pragma unroll
        for (int r = 0; r < 32; r += 8) {
            long si = (long)(kt * 32 + ty + r) * 128 + nt * 32 + tx;
            float v = src[si];
            ts[ty + r][tx] = v;
            g_w2f[(long)e * 256 * 128 + si] = __float2half_rn(v);
        }
        __syncthreads();
        #pragma unroll
        for (int r = 0; r < 32; r += 8) {
            float v = ts[tx][ty + r];
            __nv_bfloat16 hi = __float2bfloat16_rn(v);
            __nv_bfloat16 lo = __float2bfloat16_rn(v - __bfloat162float(hi));
            long o = (long)e * 128 * 256 + (long)(nt * 32 + ty + r) * 256 + kt * 32 + tx;
            g_w2thi[o] = hi; g_w2tlo[o] = lo;
        }
    }
}

// ---------------- kernel: gate (+ X splits + output zeroing) ----------------
__global__ void __launch_bounds__(256) moe_gate(
    const float* __restrict__ x, const float* __restrict__ Wp,
    const float* __restrict__ bp, const float* __restrict__ Ee,
    float* __restrict__ outbuf, long zero_lo, long zero_hi,
    float* __restrict__ pout, int n)
{
    __shared__ float WpS[DIM_IN * 64];
    __shared__ float EeS[64 * NEXP];
    __shared__ float hS[8][64];
    __shared__ float pS[8][8];
    __shared__ int   cntS[NEXP];

    int tid = threadIdx.x, warp = tid >> 5, lane = tid & 31;
    for (int i = tid; i < DIM_IN * 64; i += 256) WpS[i] = Wp[i];
    for (int i = tid; i < 64 * NEXP; i += 256)   EeS[i] = Ee[i];
    if (tid < NEXP) cntS[tid] = 0;
    if (blockIdx.x == 0 && tid == 0) {
        for (long i = zero_lo; i < zero_hi; i++) outbuf[i] = 0.f;
    }
    __syncthreads();

    const float4 z4 = make_float4(0.f, 0.f, 0.f, 0.f);

    for (int tok = blockIdx.x * 8 + warp; tok < n; tok += gridDim.x * 8) {
        float xr[4];
        #pragma unroll
        for (int i = 0; i < 4; i++) xr[i] = x[(long)tok * DIM_IN + lane + 32 * i];

        reinterpret_cast<float4*>(outbuf + (long)tok * DIM_OUT)[lane] = z4;

        #pragma unroll
        for (int i = 0; i < 4; i++) {
            long o = (long)tok * DIM_IN + lane + 32 * i;
            __nv_bfloat16 bh = __float2bfloat16_rn(xr[i]);
            g_xbhi[o] = bh;
            g_xblo[o] = __float2bfloat16_rn(xr[i] - __bfloat162float(bh));
            __half fh = __float2half_rn(xr[i]);
            g_xfhi[o] = fh;
            g_xflo[o] = __float2half_rn(xr[i] - __half2float(fh));
        }

        float h0 = bp[lane], h1 = bp[lane + 32];
        #pragma unroll
        for (int d = 0; d < DIM_IN; d++) {
            float xd = __shfl_sync(0xffffffffu, xr[d >> 5], d & 31);
            h0 += xd * WpS[d * 64 + lane];
            h1 += xd * WpS[d * 64 + lane + 32];
        }
        hS[warp][lane] = h0;
        hS[warp][lane + 32] = h1;
        __syncwarp();

        if (lane < NEXP) {
            float lg = 0.f;
            #pragma unroll
            for (int e2 = 0; e2 < 64; e2++) lg += hS[warp][e2] * EeS[e2 * NEXP + lane];
            float p = 1.f / (1.f + expf(-lg * 0.2f));   // tau = 5
            pS[warp][lane] = p;
            if (pout) pout[(long)tok * NEXP + lane] = p;
        }
        __syncwarp();

        if (lane == 0) {
            float v0 = -1.f, v1 = -1.f; int i0 = 0, i1 = 0;
            #pragma unroll
            for (int j = 0; j < NEXP; j++) {
                float pv = pS[warp][j];
                if (pv > v0) { v1 = v0; i1 = i0; v0 = pv; i0 = j; }
                else if (pv > v1) { v1 = pv; i1 = j; }
            }
            float s = v0 + v1 + 1e-10f;
            g_tokE[tok] = i0 | (i1 << 8);
            g_tokW[tok] = make_float2(v0 / s, v1 / s);
            atomicAdd(&cntS[i0], 1);
            atomicAdd(&cntS[i1], 1);
        }
        __syncwarp();
    }
    __syncthreads();
    if (tid < NEXP) atomicAdd(&g_counts[tid], cntS[tid]);
}

// ---------------- kernel: scan + tile map ----------------
__global__ void moe_build() {
    if (threadIdx.x == 0) {
        int off = 0, tile = 0;
        for (int e = 0; e < NEXP; e++) {
            int c = g_counts[e];
            g_cursor[e] = off;
            for (int t = 0; t < c && tile < MAXTILES; t += 128) {
                g_tileExpert[tile] = e;
                g_tileStart[tile]  = off + t;
                g_tileRows[tile]   = min(128, c - t);
                tile++;
            }
            off += c;
        }
        g_numTiles = tile;
    }
}

// ---------------- kernel: scatter ----------------
__global__ void __launch_bounds__(256) moe_scatter(int n) {
    __shared__ int cnt[NEXP];
    __shared__ int base[NEXP];
    int tid = threadIdx.x;
    if (tid < NEXP) cnt[tid] = 0;
    __syncthreads();

    int tok = blockIdx.x * 256 + tid;
    int e0 = 0, e1 = 0, r0 = 0, r1 = 0; float2 w = make_float2(0.f, 0.f);
    bool ok = (tok < n);
    if (ok) {
        int e01 = g_tokE[tok];
        w = g_tokW[tok];
        e0 = e01 & 255; e1 = (e01 >> 8) & 255;
        r0 = atomicAdd(&cnt[e0], 1);
        r1 = atomicAdd(&cnt[e1], 1);
    }
    __syncthreads();
    if (tid < NEXP) base[tid] = atomicAdd(&g_cursor[tid], cnt[tid]);
    __syncthreads();
    if (ok) {
        int p0 = base[e0] + r0; g_rowToken[p0] = tok; g_rowW[p0] = w.x;
        int p1 = base[e1] + r1; g_rowToken[p1] = tok; g_rowW[p1] = w.y;
    }
}

// ================= tcgen05 expert (probe-validated primitives only) =================
#if HAS_TCGEN05
__device__ __forceinline__ uint32_t smem_u32(const void* p) {
    uint32_t a;
    asm("{ .reg .u64 t; cvta.to.shared.u64 t, %1; cvt.u32.u64 %0, t; }" : "=r"(a) : "l"(p));
    return a;
}
__device__ __forceinline__ uint32_t elect_one() {
    uint32_t p;
    asm volatile("{ .reg .pred p; elect.sync _|p, 0xFFFFFFFF; selp.b32 %0, 1, 0, p; }" : "=r"(p));
    return p;
}
#define TC_ALLOC(sm, n)  asm volatile("tcgen05.alloc.cta_group::1.sync.aligned.shared::cta.b32 [%0], %1;" :: "r"(sm), "r"(n) : "memory")
#define TC_DEALLOC(t, n) asm volatile("tcgen05.dealloc.cta_group::1.sync.aligned.b32 %0, %1;" :: "r"(t), "r"(n))
#define TC_COMMIT(mb)    asm volatile("tcgen05.commit.cta_group::1.mbarrier::arrive::one.shared::cluster.b64 [%0];" :: "r"(mb) : "memory")
#define TC_WAIT_LD()     asm volatile("tcgen05.wait::ld.sync.aligned;" ::: "memory")
#define TC_WAIT_ST()     asm volatile("tcgen05.wait::st.sync.aligned;" ::: "memory")
#define TC_FENCE_BEFORE() asm volatile("tcgen05.fence::before_thread_sync;" ::: "memory")
#define TC_FENCE_AFTER()  asm volatile("tcgen05.fence::after_thread_sync;" ::: "memory")
#define FENCE_ASYNC()    asm volatile("fence.proxy.async.shared::cta;" ::: "memory")
#define MBAR_INIT(mb, c) asm volatile("mbarrier.init.shared.b64 [%0], %1;" :: "r"(mb), "r"(c) : "memory")
#define MBAR_INVAL(mb)   asm volatile("mbarrier.inval.shared.b64 [%0];" :: "r"(mb) : "memory")
#define MBAR_WAIT(mb, ph) do {                                            \
    uint32_t _m = (mb), _p = (ph), _d;                                    \
    asm volatile("{ .reg .pred p; mbarrier.try_wait.parity.acquire.cta.shared::cta.b64 p, [%1], %2; selp.b32 %0, 1, 0, p; }" \
        : "=r"(_d) : "r"(_m), "r"(_p) : "memory");                        \
    if (!_d) {                                                            \
        asm volatile("{ .reg .pred P1; WL%=: mbarrier.try_wait.parity.acquire.cta.shared::cta.b64 P1, [%0], %1, 0x989680; @P1 bra.uni WD%=; bra.uni WL%=; WD%=: }" \
            :: "r"(_m), "r"(_p) : "memory");                              \
    }                                                                     \
} while (0)
#define TC_LD_X32(r, t)                                                   \
    asm volatile("tcgen05.ld.sync.aligned.32x32b.x32.b32 "                \
        "{%0,%1,%2,%3,%4,%5,%6,%7,%8,%9,%10,%11,%12,%13,%14,%15,"        \
        "%16,%17,%18,%19,%20,%21,%22,%23,%24,%25,%26,%27,%28,%29,%30,%31}, [%32];" \
        : "=r"((r)[0]),"=r"((r)[1]),"=r"((r)[2]),"=r"((r)[3]),"=r"((r)[4]),"=r"((r)[5]),"=r"((r)[6]),"=r"((r)[7]), \
          "=r"((r)[8]),"=r"((r)[9]),"=r"((r)[10]),"=r"((r)[11]),"=r"((r)[12]),"=r"((r)[13]),"=r"((r)[14]),"=r"((r)[15]), \
          "=r"((r)[16]),"=r"((r)[17]),"=r"((r)[18]),"=r"((r)[19]),"=r"((r)[20]),"=r"((r)[21]),"=r"((r)[22]),"=r"((r)[23]), \
          "=r"((r)[24]),"=r"((r)[25]),"=r"((r)[26]),"=r"((r)[27]),"=r"((r)[28]),"=r"((r)[29]),"=r"((r)[30]),"=r"((r)[31]) \
        : "r"(t))
#define TC_ST_X16(t, r)                                                   \
    asm volatile("tcgen05.st.sync.aligned.32x32b.x16.b32 [%0], "          \
        "{%1,%2,%3,%4,%5,%6,%7,%8,%9,%10,%11,%12,%13,%14,%15,%16};"      \
        :: "r"(t),                                                        \
           "r"((r)[0]),"r"((r)[1]),"r"((r)[2]),"r"((r)[3]),"r"((r)[4]),"r"((r)[5]),"r"((r)[6]),"r"((r)[7]), \
           "r"((r)[8]),"r"((r)[9]),"r"((r)[10]),"r"((r)[11]),"r"((r)[12]),"r"((r)[13]),"r"((r)[14]),"r"((r)[15]) \
        : "memory")
#define TC_ST_X64(t, r)                                                   \
    asm volatile("tcgen05.st.sync.aligned.32x32b.x64.b32 [%0], "          \
        "{%1,%2,%3,%4,%5,%6,%7,%8,%9,%10,%11,%12,%13,%14,%15,%16,"       \
        "%17,%18,%19,%20,%21,%22,%23,%24,%25,%26,%27,%28,%29,%30,%31,%32," \
        "%33,%34,%35,%36,%37,%38,%39,%40,%41,%42,%43,%44,%45,%46,%47,%48," \
        "%49,%50,%51,%52,%53,%54,%55,%56,%57,%58,%59,%60,%61,%62,%63,%64};" \
        :: "r"(t),                                                        \
           "r"((r)[0]),"r"((r)[1]),"r"((r)[2]),"r"((r)[3]),"r"((r)[4]),"r"((r)[5]),"r"((r)[6]),"r"((r)[7]), \
           "r"((r)[8]),"r"((r)[9]),"r"((r)[10]),"r"((r)[11]),"r"((r)[12]),"r"((r)[13]),"r"((r)[14]),"r"((r)[15]), \
           "r"((r)[16]),"r"((r)[17]),"r"((r)[18]),"r"((r)[19]),"r"((r)[20]),"r"((r)[21]),"r"((r)[22]),"r"((r)[23]), \
           "r"((r)[24]),"r"((r)[25]),"r"((r)[26]),"r"((r)[27]),"r"((r)[28]),"r"((r)[29]),"r"((r)[30]),"r"((r)[31]), \
           "r"((r)[32]),"r"((r)[33]),"r"((r)[34]),"r"((r)[35]),"r"((r)[36]),"r"((r)[37]),"r"((r)[38]),"r"((r)[39]), \
           "r"((r)[40]),"r"((r)[41]),"r"((r)[42]),"r"((r)[43]),"r"((r)[44]),"r"((r)[45]),"r"((r)[46]),"r"((r)[47]), \
           "r"((r)[48]),"r"((r)[49]),"r"((r)[50]),"r"((r)[51]),"r"((r)[52]),"r"((r)[53]),"r"((r)[54]),"r"((r)[55]), \
           "r"((r)[56]),"r"((r)[57]),"r"((r)[58]),"r"((r)[59]),"r"((r)[60]),"r"((r)[61]),"r"((r)[62]),"r"((r)[63]) \
        : "memory")

__device__ __forceinline__ void mma_f16_ts(uint32_t d, uint32_t a_tmem, uint64_t bd,
                                           uint32_t idesc, bool en) {
    uint32_t e = en ? 1u : 0u;
    asm volatile(
        "{\n\t.reg .pred p;\n\tsetp.ne.u32 p, %5, 0;\n\t"
        "tcgen05.mma.cta_group::1.kind::f16 [%0], [%1], %2, %3, {%4, %4, %4, %4}, p;\n\t}"
        :: "r"(d), "r"(a_tmem), "l"(bd), "r"(idesc), "r"(0u), "r"(e) : "memory");
}
static constexpr uint64_t DESC_BASE =
    (uint64_t(2) << 61) | (uint64_t(1) << 46) | (uint64_t(64) << 32) | (uint64_t(1) << 16);
__device__ __forceinline__ uint64_t mkdesc(uint32_t a) {
    return DESC_BASE | ((uint64_t)(a >> 4) & 0x3FFF);
}
__device__ __forceinline__ uint32_t aoff(int row, int kcol, int nAtomRows) {
    uint32_t b = ((uint32_t)((kcol >> 6) * nAtomRows + (row >> 3)) << 10)
               + ((uint32_t)(row & 7) << 7) + ((uint32_t)(kcol & 63) << 1);
    return b ^ ((b >> 3) & 0x70);
}
#define IDESC32 0x8080490u   // exact probe-validated idesc: f32 acc, bf16, M=128, N=32
// TMEM cols: X hi@0..63 lo@64..127 ; D1@128..383 ; Hhi@0..127 Hlo@384..511 ; D2@128..255
#endif  // HAS_TCGEN05

#define SMEM_TC (131072 + 1024)

__global__ void __cluster_dims__(1, 1, 1) __launch_bounds__(128, 1) moe_expert_tc(
    const float* __restrict__ b1, const float* __restrict__ b2,
    float* __restrict__ out)
{
#if HAS_TCGEN05
    int tile = blockIdx.x;
    if (tile >= g_numTiles) return;
    int e        = g_tileExpert[tile];
    int rowStart = g_tileStart[tile];
    int nRows    = g_tileRows[tile];

    extern __shared__ unsigned char smraw[];
    unsigned char* sm = (unsigned char*)(((uintptr_t)smraw + 1023) & ~(uintptr_t)1023);
    uint32_t smb = smem_u32(sm);

    __shared__ uint32_t tmemS;
    __shared__ __align__(8) unsigned long long mbars[2];
    __shared__ int   tokS[128];
    __shared__ float wS[128];
    __shared__ float b1s[256];
    __shared__ float b2s[128];

    int tid = threadIdx.x, warp = tid >> 5;
    uint32_t mb0 = smem_u32(&mbars[0]);
    uint32_t mb1 = smem_u32(&mbars[1]);
    uint32_t woff = (uint32_t)warp << 21;

    if (warp == 0) { TC_ALLOC(smem_u32(&tmemS), 512); }
    if (tid == 0) { MBAR_INIT(mb0, 1); MBAR_INIT(mb1, 1); }

    {
        int tok = -1; float w = 0.f;
        if (tid < nRows) { tok = g_rowToken[rowStart + tid]; w = g_rowW[rowStart + tid]; }
        tokS[tid] = tok; wS[tid] = w;
        b1s[tid]       = b1[(long)e * DIM_HID + tid];
        b1s[tid + 128] = b1[(long)e * DIM_HID + tid + 128];
        b2s[tid]       = b2[(long)e * DIM_OUT + tid];
    }
    __syncthreads();
    uint32_t tmem = tmemS;

    // ---- W1T (256n x 128k) bf16 planes -> SMEM blocked atoms (32 atom rows) ----
    const uint4* w1h4 = (const uint4*)(g_w1thi + (long)e * 256 * 128);
    const uint4* w1l4 = (const uint4*)(g_w1tlo + (long)e * 256 * 128);
    #pragma unroll 4
    for (int i = tid; i < 256 * 16; i += 128) {
        int r = i >> 4, u = i & 15, kc = u << 3;
        uint32_t o = aoff(r, kc, 32);
        *(uint4*)(sm + o)         = w1h4[i];
        *(uint4*)(sm + 65536 + o) = w1l4[i];
    }

    // ---- X row (tid) -> TMEM cols hi@0..63, lo@64..127 ----
    {
        int tok = tokS[tid];
        uint32_t xr[64];
        if (tok >= 0) {
            const uint4* p = (const uint4*)(g_xbhi + (long)tok * DIM_IN);
            #pragma unroll
            for (int u = 0; u < 16; u++) { uint4 v = p[u];
                xr[u*4+0]=v.x; xr[u*4+1]=v.y; xr[u*4+2]=v.z; xr[u*4+3]=v.w; }
        } else {
            #pragma unroll
            for (int j = 0; j < 64; j++) xr[j] = 0u;
        }
        TC_ST_X64(tmem + 0 + woff, xr);
        if (tok >= 0) {
            const uint4* p = (const uint4*)(g_xblo + (long)tok * DIM_IN);
            #pragma unroll
            for (int u = 0; u < 16; u++) { uint4 v = p[u];
                xr[u*4+0]=v.x; xr[u*4+1]=v.y; xr[u*4+2]=v.z; xr[u*4+3]=v.w; }
        }
        TC_ST_X64(tmem + 64 + woff, xr);
        TC_WAIT_ST();
    }
    FENCE_ASYNC();
    TC_FENCE_BEFORE();
    __syncthreads();

    // ---- GEMM1: D1[128..383] = X @ W1T^T  (8 N-tiles x 3 splits x 8 K-steps, N=32 each) ----
    if (warp == 0) {
        TC_FENCE_AFTER();
        if (elect_one()) {
            uint64_t bH = mkdesc(smb), bL = mkdesc(smb + 65536);
            for (int nt = 0; nt < 8; nt++) {
                uint32_t d = tmem + 128 + nt * 32;
                #pragma unroll
                for (int sp = 0; sp < 3; sp++) {
                    uint32_t abase = tmem + ((sp == 2) ? 64 : 0);
                    uint64_t bb = ((sp == 1) ? bL : bH) + (uint64_t)nt * 256;
                    #pragma unroll
                    for (int s = 0; s < 8; s++) {
                        uint64_t bd = bb + (uint64_t)(s >> 2) * 2048 + (uint64_t)(s & 3) * 2;
                        mma_f16_ts(d, abase + s * 8, bd, IDESC32, !(sp == 0 && s == 0));
                    }
                }
            }
            TC_COMMIT(mb0);
        }
    }
    MBAR_WAIT(mb0, 0);
    TC_FENCE_AFTER();

    // ---- H = relu(D1 + b1) -> TMEM Hhi@0..127, Hlo@384..511 ----
    #pragma unroll
    for (int cc = 0; cc < 8; cc++) {
        uint32_t rg[32];
        TC_LD_X32(rg, tmem + 128 + cc * 32);
        TC_WAIT_LD();
        uint32_t hh[16], ll[16];
        #pragma unroll
        for (int j = 0; j < 16; j++) {
            float v0 = __uint_as_float(rg[2*j])   + b1s[cc*32 + 2*j];
            float v1 = __uint_as_float(rg[2*j+1]) + b1s[cc*32 + 2*j+1];
            v0 = v0 > 0.f ? v0 : 0.f;
            v1 = v1 > 0.f ? v1 : 0.f;
            __nv_bfloat16 h0 = __float2bfloat16_rn(v0);
            __nv_bfloat16 h1 = __float2bfloat16_rn(v1);
            __nv_bfloat16 l0 = __float2bfloat16_rn(v0 - __bfloat162float(h0));
            __nv_bfloat16 l1 = __float2bfloat16_rn(v1 - __bfloat162float(h1));
            hh[j] = (uint32_t)__bfloat16_as_ushort(h0) | ((uint32_t)__bfloat16_as_ushort(h1) << 16);
            ll[j] = (uint32_t)__bfloat16_as_ushort(l0) | ((uint32_t)__bfloat16_as_ushort(l1) << 16);
        }
        TC_ST_X16(tmem + 0   + cc * 16 + woff, hh);
        TC_ST_X16(tmem + 384 + cc * 16 + woff, ll);
    }
    TC_WAIT_ST();

    // ---- W2T (128n x 256k) bf16 planes -> SMEM (16 atom rows), overwriting W1T ----
    const uint4* w2h4 = (const uint4*)(g_w2thi + (long)e * 128 * 256);
    const uint4* w2l4 = (const uint4*)(g_w2tlo + (long)e * 128 * 256);
    #pragma unroll 4
    for (int i = tid; i < 128 * 32; i += 128) {
        int r = i >> 5, u = i & 31, kc = u << 3;
        uint32_t o = aoff(r, kc, 16);
        *(uint4*)(sm + o)         = w2h4[i];
        *(uint4*)(sm + 65536 + o) = w2l4[i];
    }
    FENCE_ASYNC();
    TC_FENCE_BEFORE();
    __syncthreads();

    // ---- GEMM2: D2[128..255] = H @ W2T^T  (4 N-tiles x 3 splits x 16 K-steps) ----
    if (warp == 0) {
        TC_FENCE_AFTER();
        if (elect_one()) {
            uint64_t bH = mkdesc(smb), bL = mkdesc(smb + 65536);
            for (int nt = 0; nt < 4; nt++) {
                uint32_t d = tmem + 128 + nt * 32;
                #pragma unroll
                for (int sp = 0; sp < 3; sp++) {
                    uint32_t abase = tmem + ((sp == 2) ? 384 : 0);
                    uint64_t bb = ((sp == 1) ? bL : bH) + (uint64_t)nt * 256;
                    #pragma unroll
                    for (int s = 0; s < 16; s++) {
                        uint64_t bd = bb + (uint64_t)(s >> 2) * 1024 + (uint64_t)(s & 3) * 2;
                        mma_f16_ts(d, abase + s * 8, bd, IDESC32, !(sp == 0 && s == 0));
                    }
                }
            }
            TC_COMMIT(mb1);
        }
    }
    MBAR_WAIT(mb1, 0);
    TC_FENCE_AFTER();

    // ---- epilogue: stage D2 -> smem, weighted atomics ----
    float* stage = (float*)sm;
    #pragma unroll
    for (int cc = 0; cc < 4; cc++) {
        uint32_t rg[32];
        TC_LD_X32(rg, tmem + 128 + cc * 32);
        TC_WAIT_LD();
        #pragma unroll
        for (int j = 0; j < 32; j++)
            stage[tid * 133 + cc * 32 + j] = __uint_as_float(rg[j]);
    }
    TC_FENCE_BEFORE();
    __syncthreads();
    if (tid == 0) { MBAR_INVAL(mb0); MBAR_INVAL(mb1); }
    if (warp == 0) { TC_DEALLOC(tmem, 512); }

    for (int i = tid; i < 128 * 128; i += 128) {
        int r = i >> 7, c = i & 127;
        int tok = tokS[r];
        if (tok >= 0)
            atomicAdd(&out[(long)tok * DIM_OUT + c], wS[r] * (stage[r * 133 + c] + b2s[c]));
    }
#endif  // HAS_TCGEN05
}

// ================= WMMA fallback (proven R7 kernel; !HAS_TCGEN05 only) =================
using FragA = wmma::fragment<wmma::matrix_a, 16, 16, 16, __half, wmma::row_major>;
using FragB = wmma::fragment<wmma::matrix_b, 16, 16, 16, __half, wmma::row_major>;
using FragC = wmma::fragment<wmma::accumulator, 16, 16, 16, float>;

#define LDA 136
#define LDB 264
#define STAGE_LD 132
#define SMEM_WMMA ((2 * 128 * LDA + 2 * 128 * LDB) * 2)

__global__ void __launch_bounds__(256, 1) moe_expert_wmma(
    const float* __restrict__ b1, const float* __restrict__ b2,
    float* __restrict__ out)
{
#if !HAS_TCGEN05
    int tile = blockIdx.x;
    if (tile >= g_numTiles) return;
    int e        = g_tileExpert[tile];
    int rowStart = g_tileStart[tile];
    int nRows    = g_tileRows[tile];

    extern __shared__ __align__(16) unsigned char smraw[];
    __half* sXhi = (__half*)smraw;
    __half* sXlo = sXhi + 128 * LDA;
    __half* sHhi = sXlo + 128 * LDA;
    __half* sHlo = sHhi + 128 * LDB;
    float* stageX = (float*)smraw;
    float* stageB = (float*)sHhi;

    __shared__ int   tokS[128];
    __shared__ float wS[128];
    __shared__ float b1s[256];
    __shared__ float b2s[128];

    int tid = threadIdx.x, warp = tid >> 5;
    int wm = warp >> 1, wn = warp & 1;
    int m0 = wm * 32;

    if (tid < 128) {
        int tok = -1; float w = 0.f;
        if (tid < nRows) { tok = g_rowToken[rowStart + tid]; w = g_rowW[rowStart + tid]; }
        tokS[tid] = tok; wS[tid] = w;
        b2s[tid] = b2[(long)e * DIM_OUT + tid];
    }
    b1s[tid] = b1[(long)e * DIM_HID + tid];
    __syncthreads();

    const uint4* xh4 = (const uint4*)g_xfhi;
    const uint4* xl4 = (const uint4*)g_xflo;
    #pragma unroll 4
    for (int i = tid; i < 128 * 16; i += 256) {
        int r = i >> 4, u = i & 15;
        uint4 vh = make_uint4(0, 0, 0, 0), vl = vh;
        int tok = tokS[r];
        if (tok >= 0) { vh = xh4[(long)tok * 16 + u]; vl = xl4[(long)tok * 16 + u]; }
        *reinterpret_cast<uint4*>(&sXhi[r * LDA + u * 8]) = vh;
        *reinterpret_cast<uint4*>(&sXlo[r * LDA + u * 8]) = vl;
    }
    const uint4* w1h4 = (const uint4*)(g_w1f + (long)e * DIM_IN * DIM_HID);
    #pragma unroll 4
    for (int i = tid; i < 128 * 32; i += 256) {
        int r = i >> 5, u = i & 31;
        *reinterpret_cast<uint4*>(&sHhi[r * LDB + u * 8]) = w1h4[i];
    }
    __syncthreads();

    FragC acc[2][8];
    #pragma unroll
    for (int mi = 0; mi < 2; mi++)
        #pragma unroll
        for (int nt = 0; nt < 8; nt++) wmma::fill_fragment(acc[mi][nt], 0.f);

    int nbase = wn * 128;
    #pragma unroll
    for (int ks = 0; ks < 8; ks++) {
        FragA ahi[2], alo[2];
        #pragma unroll
        for (int mi = 0; mi < 2; mi++) {
            wmma::load_matrix_sync(ahi[mi], &sXhi[(m0 + mi * 16) * LDA + ks * 16], LDA);
            wmma::load_matrix_sync(alo[mi], &sXlo[(m0 + mi * 16) * LDA + ks * 16], LDA);
        }
        #pragma unroll
        for (int nt = 0; nt < 8; nt++) {
            FragB b;
            wmma::load_matrix_sync(b, &sHhi[(ks * 16) * LDB + nbase + nt * 16], LDB);
            #pragma unroll
            for (int mi = 0; mi < 2; mi++) {
                wmma::mma_sync(acc[mi][nt], ahi[mi], b, acc[mi][nt]);
                wmma::mma_sync(acc[mi][nt], alo[mi], b, acc[mi][nt]);
            }
        }
    }
    __syncthreads();

    #pragma unroll
    for (int h = 0; h < 2; h++) {
        if (wn == h) {
            #pragma unroll
            for (int mi = 0; mi < 2; mi++)
                #pragma unroll
                for (int nt = 0; nt < 8; nt++)
                    wmma::store_matrix_sync(&stageX[(m0 + mi * 16) * STAGE_LD + nt * 16],
                                            acc[mi][nt], STAGE_LD, wmma::mem_row_major);
        }
        __syncthreads();
        for (int i = tid; i < 128 * 128; i += 256) {
            int r = i >> 7, c = i & 127;
            float v = stageX[r * STAGE_LD + c] + b1s[h * 128 + c];
            v = v > 0.f ? v : 0.f;
            __half hh = __float2half_rn(v);
            sHhi[r * LDB + h * 128 + c] = hh;
            sHlo[r * LDB + h * 128 + c] = __float2half_rn(v - __half2float(hh));
        }
        __syncthreads();
    }

    const uint4* w2h4 = (const uint4*)(g_w2f + (long)e * DIM_HID * DIM_OUT);
    #pragma unroll 4
    for (int i = tid; i < 2 * 128 * 16; i += 256) {
        int ch = i >= 128 * 16;
        int j = i - ch * 128 * 16;
        int r = j >> 4, u = j & 15;
        __half* dst = ch ? sXlo : sXhi;
        *reinterpret_cast<uint4*>(&dst[r * LDA + u * 8]) = w2h4[(ch * 128 + r) * 16 + u];
    }
    __syncthreads();

    FragC acc2[2][4];
    #pragma unroll
    for (int mi = 0; mi < 2; mi++)
        #pragma unroll
        for (int nt = 0; nt < 4; nt++) wmma::fill_fragment(acc2[mi][nt], 0.f);

    #pragma unroll
    for (int ch = 0; ch < 2; ch++) {
        const __half* Bp = ch ? sXlo : sXhi;
        #pragma unroll
        for (int ks = 0; ks < 8; ks++) {
            FragA ahi[2], alo[2];
            #pragma unroll
            for (int mi = 0; mi < 2; mi++) {
                wmma::load_matrix_sync(ahi[mi], &sHhi[(m0 + mi * 16) * LDB + ch * 128 + ks * 16], LDB);
                wmma::load_matrix_sync(alo[mi], &sHlo[(m0 + mi * 16) * LDB + ch * 128 + ks * 16], LDB);
            }
            #pragma unroll
            for (int nt = 0; nt < 4; nt++) {
                FragB b;
                wmma::load_matrix_sync(b, &Bp[(ks * 16) * LDA + wn * 64 + nt * 16], LDA);
                #pragma unroll
                for (int mi = 0; mi < 2; mi++) {
                    wmma::mma_sync(acc2[mi][nt], ahi[mi], b, acc2[mi][nt]);
                    wmma::mma_sync(acc2[mi][nt], alo[mi], b, acc2[mi][nt]);
                }
            }
        }
    }
    __syncthreads();

    #pragma unroll
    for (int mi = 0; mi < 2; mi++)
        #pragma unroll
        for (int nt = 0; nt < 4; nt++)
            wmma::store_matrix_sync(&stageB[(m0 + mi * 16) * STAGE_LD + wn * 64 + nt * 16],
                                    acc2[mi][nt], STAGE_LD, wmma::mem_row_major);
    __syncthreads();

    for (int i = tid; i < 128 * DIM_OUT; i += 256) {
        int r = i >> 7, c = i & 127;
        int tok = tokS[r];
        if (tok >= 0)
            atomicAdd(&out[(long)tok * DIM_OUT + c],
                      wS[r] * (stageB[r * STAGE_LD + c] + b2s[c]));
    }
#endif  // !HAS_TCGEN05
}

// ---------------- launch ----------------
extern "C" void kernel_launch(void* const* d_in, const int* in_sizes, int n_in,
                              void* d_out, int out_size) {
    const float* x  = (const float*)d_in[0];
    const float* Wp = (const float*)d_in[1];
    const float* bp = (const float*)d_in[2];
    const float* Ee = (const float*)d_in[3];
    const float* W1 = (const float*)d_in[4];
    const float* b1 = (const float*)d_in[5];
    const float* W2 = (const float*)d_in[6];
    const float* b2 = (const float*)d_in[7];
    float* out = (float*)d_out;

    int n = in_sizes[0] / DIM_IN;

    float* pout = nullptr;
    long need = (long)n * DIM_OUT + (long)n * NEXP;
    long zlo = (long)n * DIM_OUT, zhi = (long)out_size;
    if ((long)out_size >= need) {
        pout = out + ((long)out_size - (long)n * NEXP);
        zhi = (long)out_size - (long)n * NEXP;
    }

    moe_prep<<<512, 256>>>(W1, W2);
    moe_gate<<<1024, 256>>>(x, Wp, bp, Ee, out, zlo, zhi, pout, n);
    moe_build<<<1, 1>>>();
    moe_scatter<<<(n + 255) / 256, 256>>>(n);

    int tiles = (2 * n + 127) / 128 + NEXP;
    cudaFuncSetAttribute(moe_expert_tc, cudaFuncAttributeMaxDynamicSharedMemorySize, SMEM_TC);
    moe_expert_tc<<<tiles, 128, SMEM_TC>>>(b1, b2, out);
    cudaFuncSetAttribute(moe_expert_wmma, cudaFuncAttributeMaxDynamicSharedMemorySize, SMEM_WMMA);
    moe_expert_wmma<<<tiles, 256, SMEM_WMMA>>>(b1, b2, out);
}

// round 10
// speedup vs baseline: 1.7909x; 1.7909x over previous
#include <cuda_runtime.h>
#include <cuda_fp16.h>
#include <mma.h>
#include <cstdint>

using namespace nvcuda;

#define DIM_IN  128
#define DIM_HID 256
#define DIM_OUT 128
#define NEXP    8
#define MAXN    65536
#define MAXROWS (2 * MAXN)
#define MAXTILES (MAXROWS / 128 + NEXP)

// ---------------- device scratch ----------------
__device__ int    g_counts[NEXP];
__device__ int    g_cursor[NEXP];
__device__ int    g_numTiles;
__device__ int    g_tileExpert[MAXTILES];
__device__ int    g_tileStart[MAXTILES];
__device__ int    g_tileRows[MAXTILES];
__device__ int    g_tokE[MAXN];
__device__ float2 g_tokW[MAXN];
__device__ int    g_rowToken[MAXROWS];
__device__ float  g_rowW[MAXROWS];

__device__ __align__(16) __half g_xf[MAXN * DIM_IN];
__device__ __align__(16) __half g_w1f[NEXP * DIM_IN * DIM_HID];  // [e][k=128][n=256]
__device__ __align__(16) __half g_w2f[NEXP * DIM_HID * DIM_OUT]; // [e][k=256][n=128]

__device__ __forceinline__ uint32_t packh2(float a, float b) {
    __half2 h = __floats2half2_rn(a, b);
    return *reinterpret_cast<uint32_t*>(&h);
}

// ---------------- kernel: weight fp16 convert + zero counts ----------------
__global__ void __launch_bounds__(256) moe_prep(
    const float* __restrict__ W1, const float* __restrict__ W2)
{
    int idx = blockIdx.x * 256 + threadIdx.x;          // 0 .. 65535
    if (blockIdx.x == 0 && threadIdx.x < NEXP) g_counts[threadIdx.x] = 0;
    if (idx < 65536) {
        float4 v = reinterpret_cast<const float4*>(W1)[idx];
        reinterpret_cast<uint2*>(g_w1f)[idx] = make_uint2(packh2(v.x, v.y), packh2(v.z, v.w));
        float4 w = reinterpret_cast<const float4*>(W2)[idx];
        reinterpret_cast<uint2*>(g_w2f)[idx] = make_uint2(packh2(w.x, w.y), packh2(w.z, w.w));
    }
}

// ---------------- kernel: gate (+ X fp16 + output zeroing) ----------------
__global__ void __launch_bounds__(256) moe_gate(
    const float* __restrict__ x, const float* __restrict__ Wp,
    const float* __restrict__ bp, const float* __restrict__ Ee,
    float* __restrict__ outbuf, long zero_lo, long zero_hi,
    float* __restrict__ pout, int n)
{
    __shared__ float WpS[DIM_IN * 64];
    __shared__ float EeS[64 * NEXP];
    __shared__ float hS[8][64];
    __shared__ float pS[8][8];
    __shared__ int   cntS[NEXP];

    int tid = threadIdx.x, warp = tid >> 5, lane = tid & 31;
    for (int i = tid; i < DIM_IN * 64; i += 256) WpS[i] = Wp[i];
    for (int i = tid; i < 64 * NEXP; i += 256)   EeS[i] = Ee[i];
    if (tid < NEXP) cntS[tid] = 0;
    if (blockIdx.x == 0 && tid == 0) {
        for (long i = zero_lo; i < zero_hi; i++) outbuf[i] = 0.f;
    }
    __syncthreads();

    const float4 z4 = make_float4(0.f, 0.f, 0.f, 0.f);

    for (int tok = blockIdx.x * 8 + warp; tok < n; tok += gridDim.x * 8) {
        float xr[4];
        #pragma unroll
        for (int i = 0; i < 4; i++) xr[i] = x[(long)tok * DIM_IN + lane + 32 * i];

        reinterpret_cast<float4*>(outbuf + (long)tok * DIM_OUT)[lane] = z4;

        #pragma unroll
        for (int i = 0; i < 4; i++)
            g_xf[(long)tok * DIM_IN + lane + 32 * i] = __float2half_rn(xr[i]);

        float h0 = bp[lane], h1 = bp[lane + 32];
        #pragma unroll
        for (int d = 0; d < DIM_IN; d++) {
            float xd = __shfl_sync(0xffffffffu, xr[d >> 5], d & 31);
            h0 += xd * WpS[d * 64 + lane];
            h1 += xd * WpS[d * 64 + lane + 32];
        }
        hS[warp][lane] = h0;
        hS[warp][lane + 32] = h1;
        __syncwarp();

        if (lane < NEXP) {
            float lg = 0.f;
            #pragma unroll
            for (int e2 = 0; e2 < 64; e2++) lg += hS[warp][e2] * EeS[e2 * NEXP + lane];
            float p = 1.f / (1.f + expf(-lg * 0.2f));   // tau = 5
            pS[warp][lane] = p;
            if (pout) pout[(long)tok * NEXP + lane] = p;
        }
        __syncwarp();

        if (lane == 0) {
            float v0 = -1.f, v1 = -1.f; int i0 = 0, i1 = 0;
            #pragma unroll
            for (int j = 0; j < NEXP; j++) {
                float pv = pS[warp][j];
                if (pv > v0) { v1 = v0; i1 = i0; v0 = pv; i0 = j; }
                else if (pv > v1) { v1 = pv; i1 = j; }
            }
            float s = v0 + v1 + 1e-10f;
            g_tokE[tok] = i0 | (i1 << 8);
            g_tokW[tok] = make_float2(v0 / s, v1 / s);
            atomicAdd(&cntS[i0], 1);
            atomicAdd(&cntS[i1], 1);
        }
        __syncwarp();
    }
    __syncthreads();
    if (tid < NEXP) atomicAdd(&g_counts[tid], cntS[tid]);
}

// ---------------- kernel: scan + tile map ----------------
__global__ void moe_build() {
    if (threadIdx.x == 0) {
        int off = 0, tile = 0;
        for (int e = 0; e < NEXP; e++) {
            int c = g_counts[e];
            g_cursor[e] = off;
            for (int t = 0; t < c && tile < MAXTILES; t += 128) {
                g_tileExpert[tile] = e;
                g_tileStart[tile]  = off + t;
                g_tileRows[tile]   = min(128, c - t);
                tile++;
            }
            off += c;
        }
        g_numTiles = tile;
    }
}

// ---------------- kernel: scatter ----------------
__global__ void __launch_bounds__(256) moe_scatter(int n) {
    __shared__ int cnt[NEXP];
    __shared__ int base[NEXP];
    int tid = threadIdx.x;
    if (tid < NEXP) cnt[tid] = 0;
    __syncthreads();

    int tok = blockIdx.x * 256 + tid;
    int e0 = 0, e1 = 0, r0 = 0, r1 = 0; float2 w = make_float2(0.f, 0.f);
    bool ok = (tok < n);
    if (ok) {
        int e01 = g_tokE[tok];
        w = g_tokW[tok];
        e0 = e01 & 255; e1 = (e01 >> 8) & 255;
        r0 = atomicAdd(&cnt[e0], 1);
        r1 = atomicAdd(&cnt[e1], 1);
    }
    __syncthreads();
    if (tid < NEXP) base[tid] = atomicAdd(&g_cursor[tid], cnt[tid]);
    __syncthreads();
    if (ok) {
        int p0 = base[e0] + r0; g_rowToken[p0] = tok; g_rowW[p0] = w.x;
        int p1 = base[e1] + r1; g_rowToken[p1] = tok; g_rowW[p1] = w.y;
    }
}

// ---------------- kernel: grouped expert GEMM (1-pass fp16, 4x2 warp tiling) ----------------
using FragA = wmma::fragment<wmma::matrix_a, 16, 16, 16, __half, wmma::row_major>;
using FragB = wmma::fragment<wmma::matrix_b, 16, 16, 16, __half, wmma::row_major>;
using FragC = wmma::fragment<wmma::accumulator, 16, 16, 16, float>;

#define LDA 136           // X / W2-chunk planes: 128 x 136 half
#define LDB 264           // W1 / H plane:        128 x 264 half
#define STAGE_LD 132
// regions: A0 (X -> W2 ch0), A1 (W2 ch1), B (W1 -> H -> fp32 stage)
#define SMEM_WMMA ((2 * 128 * LDA + 128 * LDB) * 2)   // 137216 B

__global__ void __launch_bounds__(256, 1) moe_expert(
    const float* __restrict__ b1, const float* __restrict__ b2,
    float* __restrict__ out)
{
    int tile = blockIdx.x;
    if (tile >= g_numTiles) return;
    int e        = g_tileExpert[tile];
    int rowStart = g_tileStart[tile];
    int nRows    = g_tileRows[tile];

    extern __shared__ __align__(16) unsigned char smraw[];
    __half* sA0 = (__half*)smraw;                  // 128 x LDA (X, then W2 chunk0)
    __half* sA1 = sA0 + 128 * LDA;                 // 128 x LDA (W2 chunk1)
    __half* sH  = sA1 + 128 * LDA;                 // 128 x LDB (W1, then H)
    float* stageX = (float*)smraw;                 // fp32 stage over A0+A1 (69632 B >= 67584)
    float* stageB = (float*)sH;                    // fp32 stage over B region

    __shared__ int   tokS[128];
    __shared__ float wS[128];
    __shared__ float b1s[256];
    __shared__ float b2s[128];

    int tid = threadIdx.x, warp = tid >> 5;
    int wm = warp >> 1, wn = warp & 1;
    int m0 = wm * 32;

    if (tid < 128) {
        int tok = -1; float w = 0.f;
        if (tid < nRows) { tok = g_rowToken[rowStart + tid]; w = g_rowW[rowStart + tid]; }
        tokS[tid] = tok; wS[tid] = w;
        b2s[tid] = b2[(long)e * DIM_OUT + tid];
    }
    b1s[tid] = b1[(long)e * DIM_HID + tid];
    __syncthreads();

    // ---- fill X (gathered fp16) into A0 ----
    const uint4* x4 = (const uint4*)g_xf;
    #pragma unroll 4
    for (int i = tid; i < 128 * 16; i += 256) {
        int r = i >> 4, u = i & 15;
        uint4 v = make_uint4(0, 0, 0, 0);
        int tok = tokS[r];
        if (tok >= 0) v = x4[(long)tok * 16 + u];
        *reinterpret_cast<uint4*>(&sA0[r * LDA + u * 8]) = v;
    }
    // ---- fill W1 [k=128][n=256] into B region ----
    const uint4* w1h4 = (const uint4*)(g_w1f + (long)e * DIM_IN * DIM_HID);
    #pragma unroll 4
    for (int i = tid; i < 128 * 32; i += 256) {
        int r = i >> 5, u = i & 31;
        *reinterpret_cast<uint4*>(&sH[r * LDB + u * 8]) = w1h4[i];
    }
    __syncthreads();

    // ---- GEMM1: Hraw[128x256] = X @ W1 ; warp tile 32 x 128 ----
    FragC acc[2][8];
    #pragma unroll
    for (int mi = 0; mi < 2; mi++)
        #pragma unroll
        for (int nt = 0; nt < 8; nt++) wmma::fill_fragment(acc[mi][nt], 0.f);

    int nbase = wn * 128;
    #pragma unroll
    for (int ks = 0; ks < 8; ks++) {
        FragA a[2];
        #pragma unroll
        for (int mi = 0; mi < 2; mi++)
            wmma::load_matrix_sync(a[mi], &sA0[(m0 + mi * 16) * LDA + ks * 16], LDA);
        #pragma unroll
        for (int nt = 0; nt < 8; nt++) {
            FragB b;
            wmma::load_matrix_sync(b, &sH[(ks * 16) * LDB + nbase + nt * 16], LDB);
            #pragma unroll
            for (int mi = 0; mi < 2; mi++)
                wmma::mma_sync(acc[mi][nt], a[mi], b, acc[mi][nt]);
        }
    }
    __syncthreads();   // X and W1 fully consumed

    // ---- H = relu(acc + b1): stage fp32 through A0+A1, fp16 into B region ----
    #pragma unroll
    for (int h = 0; h < 2; h++) {
        if (wn == h) {
            #pragma unroll
            for (int mi = 0; mi < 2; mi++)
                #pragma unroll
                for (int nt = 0; nt < 8; nt++)
                    wmma::store_matrix_sync(&stageX[(m0 + mi * 16) * STAGE_LD + nt * 16],
                                            acc[mi][nt], STAGE_LD, wmma::mem_row_major);
        }
        __syncthreads();
        for (int i = tid; i < 128 * 128; i += 256) {
            int r = i >> 7, c = i & 127;
            float v = stageX[r * STAGE_LD + c] + b1s[h * 128 + c];
            v = v > 0.f ? v : 0.f;
            sH[r * LDB + h * 128 + c] = __float2half_rn(v);
        }
        __syncthreads();
    }

    // ---- fill BOTH W2 K-chunks (ch0 -> A0, ch1 -> A1) ----
    const uint4* w2h4 = (const uint4*)(g_w2f + (long)e * DIM_HID * DIM_OUT);
    #pragma unroll 4
    for (int i = tid; i < 2 * 128 * 16; i += 256) {
        int ch = i >= 128 * 16;
        int j = i - ch * 128 * 16;
        int r = j >> 4, u = j & 15;
        __half* dst = ch ? sA1 : sA0;
        *reinterpret_cast<uint4*>(&dst[r * LDA + u * 8]) = w2h4[(ch * 128 + r) * 16 + u];
    }
    __syncthreads();

    // ---- GEMM2: C[128x128] = H @ W2 ; warp tile 32 x 64 ----
    FragC acc2[2][4];
    #pragma unroll
    for (int mi = 0; mi < 2; mi++)
        #pragma unroll
        for (int nt = 0; nt < 4; nt++) wmma::fill_fragment(acc2[mi][nt], 0.f);

    #pragma unroll
    for (int ch = 0; ch < 2; ch++) {
        const __half* Bp = ch ? sA1 : sA0;
        #pragma unroll
        for (int ks = 0; ks < 8; ks++) {
            FragA a[2];
            #pragma unroll
            for (int mi = 0; mi < 2; mi++)
                wmma::load_matrix_sync(a[mi], &sH[(m0 + mi * 16) * LDB + ch * 128 + ks * 16], LDB);
            #pragma unroll
            for (int nt = 0; nt < 4; nt++) {
                FragB b;
                wmma::load_matrix_sync(b, &Bp[(ks * 16) * LDA + wn * 64 + nt * 16], LDA);
                #pragma unroll
                for (int mi = 0; mi < 2; mi++)
                    wmma::mma_sync(acc2[mi][nt], a[mi], b, acc2[mi][nt]);
            }
        }
    }
    __syncthreads();   // H fully consumed

    // ---- epilogue: out[tok] += w * (C + b2) ----
    #pragma unroll
    for (int mi = 0; mi < 2; mi++)
        #pragma unroll
        for (int nt = 0; nt < 4; nt++)
            wmma::store_matrix_sync(&stageB[(m0 + mi * 16) * STAGE_LD + wn * 64 + nt * 16],
                                    acc2[mi][nt], STAGE_LD, wmma::mem_row_major);
    __syncthreads();

    for (int i = tid; i < 128 * DIM_OUT; i += 256) {
        int r = i >> 7, c = i & 127;
        int tok = tokS[r];
        if (tok >= 0)
            atomicAdd(&out[(long)tok * DIM_OUT + c],
                      wS[r] * (stageB[r * STAGE_LD + c] + b2s[c]));
    }
}

// ---------------- launch ----------------
extern "C" void kernel_launch(void* const* d_in, const int* in_sizes, int n_in,
                              void* d_out, int out_size) {
    const float* x  = (const float*)d_in[0];
    const float* Wp = (const float*)d_in[1];
    const float* bp = (const float*)d_in[2];
    const float* Ee = (const float*)d_in[3];
    const float* W1 = (const float*)d_in[4];
    const float* b1 = (const float*)d_in[5];
    const float* W2 = (const float*)d_in[6];
    const float* b2 = (const float*)d_in[7];
    float* out = (float*)d_out;

    int n = in_sizes[0] / DIM_IN;

    float* pout = nullptr;
    long need = (long)n * DIM_OUT + (long)n * NEXP;
    long zlo = (long)n * DIM_OUT, zhi = (long)out_size;
    if ((long)out_size >= need) {
        pout = out + ((long)out_size - (long)n * NEXP);
        zhi = (long)out_size - (long)n * NEXP;
    }

    moe_prep<<<256, 256>>>(W1, W2);
    moe_gate<<<1024, 256>>>(x, Wp, bp, Ee, out, zlo, zhi, pout, n);
    moe_build<<<1, 1>>>();
    moe_scatter<<<(n + 255) / 256, 256>>>(n);

    int tiles = (2 * n + 127) / 128 + NEXP;
    cudaFuncSetAttribute(moe_expert, cudaFuncAttributeMaxDynamicSharedMemorySize, SMEM_WMMA);
    moe_expert<<<tiles, 256, SMEM_WMMA>>>(b1, b2, out);
}

// round 11
// speedup vs baseline: 1.8022x; 1.0063x over previous
#include <cuda_runtime.h>
#include <cuda_fp16.h>
#include <mma.h>
#include <cstdint>

using namespace nvcuda;

#define DIM_IN  128
#define DIM_HID 256
#define DIM_OUT 128
#define NEXP    8
#define MAXN    65536
#define MAXROWS (2 * MAXN)
#define MAXTILES (MAXROWS / 128 + NEXP)

// ---------------- device scratch ----------------
__device__ int    g_counts[NEXP];
__device__ int    g_cursor[NEXP];
__device__ int    g_numTiles;
__device__ int    g_tileExpert[MAXTILES];
__device__ int    g_tileStart[MAXTILES];
__device__ int    g_tileRows[MAXTILES];
__device__ int    g_tokE[MAXN];
__device__ float2 g_tokW[MAXN];
__device__ int    g_rowToken[MAXROWS];
__device__ float  g_rowW[MAXROWS];

__device__ __align__(16) __half g_xf[MAXN * DIM_IN];
__device__ __align__(16) __half g_w1f[NEXP * DIM_IN * DIM_HID];  // [e][k=128][n=256]
__device__ __align__(16) __half g_w2f[NEXP * DIM_HID * DIM_OUT]; // [e][k=256][n=128]

__device__ __forceinline__ uint32_t packh2(float a, float b) {
    __half2 h = __floats2half2_rn(a, b);
    return *reinterpret_cast<uint32_t*>(&h);
}
__device__ __forceinline__ uint32_t smem_u32(const void* p) {
    uint32_t a;
    asm("{ .reg .u64 t; cvta.to.shared.u64 t, %1; cvt.u32.u64 %0, t; }" : "=r"(a) : "l"(p));
    return a;
}
#define CP_ASYNC16(dst, src) asm volatile("cp.async.cg.shared.global [%0], [%1], 16;" :: "r"(dst), "l"(src))
#define CP_COMMIT()          asm volatile("cp.async.commit_group;" ::: "memory")
#define CP_WAIT1()           asm volatile("cp.async.wait_group 1;" ::: "memory")

// ---------------- kernel: weight fp16 convert + zero counts ----------------
__global__ void __launch_bounds__(256) moe_prep(
    const float* __restrict__ W1, const float* __restrict__ W2)
{
    int idx = blockIdx.x * 256 + threadIdx.x;          // 0 .. 65535
    if (blockIdx.x == 0 && threadIdx.x < NEXP) g_counts[threadIdx.x] = 0;
    if (idx < 65536) {
        float4 v = reinterpret_cast<const float4*>(W1)[idx];
        reinterpret_cast<uint2*>(g_w1f)[idx] = make_uint2(packh2(v.x, v.y), packh2(v.z, v.w));
        float4 w = reinterpret_cast<const float4*>(W2)[idx];
        reinterpret_cast<uint2*>(g_w2f)[idx] = make_uint2(packh2(w.x, w.y), packh2(w.z, w.w));
    }
}

// ---------------- kernel: gate (+ X fp16 + output zeroing) ----------------
__global__ void __launch_bounds__(256) moe_gate(
    const float* __restrict__ x, const float* __restrict__ Wp,
    const float* __restrict__ bp, const float* __restrict__ Ee,
    float* __restrict__ outbuf, long zero_lo, long zero_hi,
    float* __restrict__ pout, int n)
{
    __shared__ float WpS[DIM_IN * 64];
    __shared__ float EeS[64 * NEXP];
    __shared__ float hS[8][64];
    __shared__ float pS[8][8];
    __shared__ int   cntS[NEXP];

    int tid = threadIdx.x, warp = tid >> 5, lane = tid & 31;
    for (int i = tid; i < DIM_IN * 64; i += 256) WpS[i] = Wp[i];
    for (int i = tid; i < 64 * NEXP; i += 256)   EeS[i] = Ee[i];
    if (tid < NEXP) cntS[tid] = 0;
    if (blockIdx.x == 0 && tid == 0) {
        for (long i = zero_lo; i < zero_hi; i++) outbuf[i] = 0.f;
    }
    __syncthreads();

    const float4 z4 = make_float4(0.f, 0.f, 0.f, 0.f);

    for (int tok = blockIdx.x * 8 + warp; tok < n; tok += gridDim.x * 8) {
        float xr[4];
        #pragma unroll
        for (int i = 0; i < 4; i++) xr[i] = x[(long)tok * DIM_IN + lane + 32 * i];

        reinterpret_cast<float4*>(outbuf + (long)tok * DIM_OUT)[lane] = z4;

        #pragma unroll
        for (int i = 0; i < 4; i++)
            g_xf[(long)tok * DIM_IN + lane + 32 * i] = __float2half_rn(xr[i]);

        float h0 = bp[lane], h1 = bp[lane + 32];
        #pragma unroll
        for (int d = 0; d < DIM_IN; d++) {
            float xd = __shfl_sync(0xffffffffu, xr[d >> 5], d & 31);
            h0 += xd * WpS[d * 64 + lane];
            h1 += xd * WpS[d * 64 + lane + 32];
        }
        hS[warp][lane] = h0;
        hS[warp][lane + 32] = h1;
        __syncwarp();

        if (lane < NEXP) {
            float lg = 0.f;
            #pragma unroll
            for (int e2 = 0; e2 < 64; e2++) lg += hS[warp][e2] * EeS[e2 * NEXP + lane];
            float p = 1.f / (1.f + expf(-lg * 0.2f));   // tau = 5
            pS[warp][lane] = p;
            if (pout) pout[(long)tok * NEXP + lane] = p;
        }
        __syncwarp();

        if (lane == 0) {
            float v0 = -1.f, v1 = -1.f; int i0 = 0, i1 = 0;
            #pragma unroll
            for (int j = 0; j < NEXP; j++) {
                float pv = pS[warp][j];
                if (pv > v0) { v1 = v0; i1 = i0; v0 = pv; i0 = j; }
                else if (pv > v1) { v1 = pv; i1 = j; }
            }
            float s = v0 + v1 + 1e-10f;
            g_tokE[tok] = i0 | (i1 << 8);
            g_tokW[tok] = make_float2(v0 / s, v1 / s);
            atomicAdd(&cntS[i0], 1);
            atomicAdd(&cntS[i1], 1);
        }
        __syncwarp();
    }
    __syncthreads();
    if (tid < NEXP) atomicAdd(&g_counts[tid], cntS[tid]);
}

// ---------------- kernel: scan + tile map ----------------
__global__ void moe_build() {
    if (threadIdx.x == 0) {
        int off = 0, tile = 0;
        for (int e = 0; e < NEXP; e++) {
            int c = g_counts[e];
            g_cursor[e] = off;
            for (int t = 0; t < c && tile < MAXTILES; t += 128) {
                g_tileExpert[tile] = e;
                g_tileStart[tile]  = off + t;
                g_tileRows[tile]   = min(128, c - t);
                tile++;
            }
            off += c;
        }
        g_numTiles = tile;
    }
}

// ---------------- kernel: scatter ----------------
__global__ void __launch_bounds__(256) moe_scatter(int n) {
    __shared__ int cnt[NEXP];
    __shared__ int base[NEXP];
    int tid = threadIdx.x;
    if (tid < NEXP) cnt[tid] = 0;
    __syncthreads();

    int tok = blockIdx.x * 256 + tid;
    int e0 = 0, e1 = 0, r0 = 0, r1 = 0; float2 w = make_float2(0.f, 0.f);
    bool ok = (tok < n);
    if (ok) {
        int e01 = g_tokE[tok];
        w = g_tokW[tok];
        e0 = e01 & 255; e1 = (e01 >> 8) & 255;
        r0 = atomicAdd(&cnt[e0], 1);
        r1 = atomicAdd(&cnt[e1], 1);
    }
    __syncthreads();
    if (tid < NEXP) base[tid] = atomicAdd(&g_cursor[tid], cnt[tid]);
    __syncthreads();
    if (ok) {
        int p0 = base[e0] + r0; g_rowToken[p0] = tok; g_rowW[p0] = w.x;
        int p1 = base[e1] + r1; g_rowToken[p1] = tok; g_rowW[p1] = w.y;
    }
}

// ---------------- kernel: persistent expert GEMM (fp16, double-buffered cp.async) ----------------
using FragA = wmma::fragment<wmma::matrix_a, 16, 16, 16, __half, wmma::row_major>;
using FragB = wmma::fragment<wmma::matrix_b, 16, 16, 16, __half, wmma::row_major>;
using FragC = wmma::fragment<wmma::accumulator, 16, 16, 16, float>;

#define LDX 136           // X / W2-chunk plane: 128 x 136 half
#define LDW 264           // W1 / H plane:       128 x 264 half
#define XB  (128 * LDX * 2)   // 34816 B
#define WB  (128 * LDW * 2)   // 67584 B
#define SMEM_EXP (2 * XB + 2 * WB)   // 204800 B

__global__ void __launch_bounds__(256, 1) moe_expert(
    const float* __restrict__ b1, const float* __restrict__ b2,
    float* __restrict__ out)
{
    extern __shared__ __align__(16) unsigned char sm[];
    __shared__ int   tokS[2][128];
    __shared__ float wS[2][128];
    __shared__ float b1s[256];
    __shared__ float b2s[128];

    int tid = threadIdx.x, warp = tid >> 5;
    int wm = warp >> 1, wn = warp & 1;
    int m0 = wm * 32;
    int numTiles = g_numTiles;
    int stride = gridDim.x;
    uint32_t smb = smem_u32(sm);
    const uint4* x4g = (const uint4*)g_xf;

    // ---- prologue: prefetch first tile into buffer 0 ----
    int t0 = blockIdx.x;
    if (t0 < numTiles && tid < 128) {
        int rs = g_tileStart[t0], nr = g_tileRows[t0];
        int tok = -1; float w = 0.f;
        if (tid < nr) { tok = g_rowToken[rs + tid]; w = g_rowW[rs + tid]; }
        tokS[0][tid] = tok; wS[0][tid] = w;
    }
    __syncthreads();
    if (t0 < numTiles) {
        int e0 = g_tileExpert[t0];
        uint32_t xb = smb;
        #pragma unroll 2
        for (int i = tid; i < 128 * 16; i += 256) {
            int r = i >> 4, u = i & 15;
            int tok = tokS[0][r]; if (tok < 0) tok = 0;
            CP_ASYNC16(xb + (uint32_t)(r * LDX + u * 8) * 2, x4g + (long)tok * 16 + u);
        }
        uint32_t wb = smb + 2 * XB;
        const uint4* w14 = (const uint4*)(g_w1f + (long)e0 * DIM_IN * DIM_HID);
        #pragma unroll 2
        for (int i = tid; i < 128 * 32; i += 256) {
            int r = i >> 5, u = i & 31;
            CP_ASYNC16(wb + (uint32_t)(r * LDW + u * 8) * 2, w14 + i);
        }
    }
    CP_COMMIT();

    int buf = 0;
    for (int t = t0; t < numTiles; t += stride, buf ^= 1) {
        int e = g_tileExpert[t];
        int ntile = t + stride;
        int nb = buf ^ 1;

        __syncthreads();   // previous epilogue complete; safe to write shared meta
        b1s[tid] = b1[(long)e * DIM_HID + tid];
        if (tid < 128) b2s[tid] = b2[(long)e * DIM_OUT + tid];
        if (ntile < numTiles && tid < 128) {
            int rs = g_tileStart[ntile], nr = g_tileRows[ntile];
            int tok = -1; float w = 0.f;
            if (tid < nr) { tok = g_rowToken[rs + tid]; w = g_rowW[rs + tid]; }
            tokS[nb][tid] = tok; wS[nb][tid] = w;
        }
        __syncthreads();

        // ---- issue next tile's prefetch (overlaps all compute below) ----
        if (ntile < numTiles) {
            int en = g_tileExpert[ntile];
            uint32_t xb = smb + (uint32_t)nb * XB;
            #pragma unroll 2
            for (int i = tid; i < 128 * 16; i += 256) {
                int r = i >> 4, u = i & 15;
                int tok = tokS[nb][r]; if (tok < 0) tok = 0;
                CP_ASYNC16(xb + (uint32_t)(r * LDX + u * 8) * 2, x4g + (long)tok * 16 + u);
            }
            uint32_t wb = smb + 2 * XB + (uint32_t)nb * WB;
            const uint4* w14 = (const uint4*)(g_w1f + (long)en * DIM_IN * DIM_HID);
            #pragma unroll 2
            for (int i = tid; i < 128 * 32; i += 256) {
                int r = i >> 5, u = i & 31;
                CP_ASYNC16(wb + (uint32_t)(r * LDW + u * 8) * 2, w14 + i);
            }
        }
        CP_COMMIT();
        CP_WAIT1();        // current tile's X/W1 are resident
        __syncthreads();

        __half* xr = (__half*)(sm + (size_t)buf * XB);
        __half* hw = (__half*)(sm + 2 * XB + (size_t)buf * WB);

        // ---- GEMM1: Hraw[128x256] = X @ W1 ----
        FragC acc[2][8];
        #pragma unroll
        for (int mi = 0; mi < 2; mi++)
            #pragma unroll
            for (int nt = 0; nt < 8; nt++) wmma::fill_fragment(acc[mi][nt], 0.f);

        int nbase = wn * 128;
        #pragma unroll
        for (int ks = 0; ks < 8; ks++) {
            FragA a[2];
            #pragma unroll
            for (int mi = 0; mi < 2; mi++)
                wmma::load_matrix_sync(a[mi], &xr[(m0 + mi * 16) * LDX + ks * 16], LDX);
            #pragma unroll
            for (int nt = 0; nt < 8; nt++) {
                FragB b;
                wmma::load_matrix_sync(b, &hw[(ks * 16) * LDW + nbase + nt * 16], LDW);
                #pragma unroll
                for (int mi = 0; mi < 2; mi++)
                    wmma::mma_sync(acc[mi][nt], a[mi], b, acc[mi][nt]);
            }
        }
        __syncthreads();   // X and W1 fully consumed

        // ---- H = relu(acc + b1): 4 phases of 64 cols, fp32 stage in dead X region ----
        float* stage = (float*)xr;   // 128 x 68 fp32 = 34816 B
        #pragma unroll
        for (int p = 0; p < 4; p++) {
            if (wn == (p >> 1)) {
                #pragma unroll
                for (int mi = 0; mi < 2; mi++)
                    #pragma unroll
                    for (int j = 0; j < 4; j++)
                        wmma::store_matrix_sync(&stage[(m0 + mi * 16) * 68 + j * 16],
                                                acc[mi][(p & 1) * 4 + j], 68, wmma::mem_row_major);
            }
            __syncthreads();
            #pragma unroll 4
            for (int i = tid; i < 128 * 64; i += 256) {
                int r = i >> 6, c = i & 63;
                float v = stage[r * 68 + c] + b1s[p * 64 + c];
                v = v > 0.f ? v : 0.f;
                hw[r * LDW + p * 64 + c] = __float2half_rn(v);
            }
            __syncthreads();
        }

        // ---- GEMM2: C[128x128] = H @ W2, two K-chunks through dead X region ----
        FragC acc2[2][4];
        #pragma unroll
        for (int mi = 0; mi < 2; mi++)
            #pragma unroll
            for (int nt = 0; nt < 4; nt++) wmma::fill_fragment(acc2[mi][nt], 0.f);

        const uint4* w24 = (const uint4*)(g_w2f + (long)e * DIM_HID * DIM_OUT);
        #pragma unroll
        for (int ch = 0; ch < 2; ch++) {
            #pragma unroll 2
            for (int i = tid; i < 128 * 16; i += 256) {
                int r = i >> 4, u = i & 15;
                *reinterpret_cast<uint4*>(&xr[r * LDX + u * 8]) = w24[(ch * 128 + r) * 16 + u];
            }
            __syncthreads();
            #pragma unroll
            for (int ks = 0; ks < 8; ks++) {
                FragA a[2];
                #pragma unroll
                for (int mi = 0; mi < 2; mi++)
                    wmma::load_matrix_sync(a[mi], &hw[(m0 + mi * 16) * LDW + ch * 128 + ks * 16], LDW);
                #pragma unroll
                for (int nt = 0; nt < 4; nt++) {
                    FragB b;
                    wmma::load_matrix_sync(b, &xr[(ks * 16) * LDX + wn * 64 + nt * 16], LDX);
                    #pragma unroll
                    for (int mi = 0; mi < 2; mi++)
                        wmma::mma_sync(acc2[mi][nt], a[mi], b, acc2[mi][nt]);
                }
            }
            __syncthreads();
        }

        // ---- epilogue: stage C (over dead H) then weighted atomics ----
        float* stC = (float*)hw;   // 128 x 132 fp32 = 67584 B
        #pragma unroll
        for (int mi = 0; mi < 2; mi++)
            #pragma unroll
            for (int nt = 0; nt < 4; nt++)
                wmma::store_matrix_sync(&stC[(m0 + mi * 16) * 132 + wn * 64 + nt * 16],
                                        acc2[mi][nt], 132, wmma::mem_row_major);
        __syncthreads();

        #pragma unroll 4
        for (int i = tid; i < 128 * DIM_OUT; i += 256) {
            int r = i >> 7, c = i & 127;
            int tok = tokS[buf][r];
            if (tok >= 0)
                atomicAdd(&out[(long)tok * DIM_OUT + c],
                          wS[buf][r] * (stC[r * 132 + c] + b2s[c]));
        }
    }
}

// ---------------- launch ----------------
extern "C" void kernel_launch(void* const* d_in, const int* in_sizes, int n_in,
                              void* d_out, int out_size) {
    const float* x  = (const float*)d_in[0];
    const float* Wp = (const float*)d_in[1];
    const float* bp = (const float*)d_in[2];
    const float* Ee = (const float*)d_in[3];
    const float* W1 = (const float*)d_in[4];
    const float* b1 = (const float*)d_in[5];
    const float* W2 = (const float*)d_in[6];
    const float* b2 = (const float*)d_in[7];
    float* out = (float*)d_out;

    int n = in_sizes[0] / DIM_IN;

    float* pout = nullptr;
    long need = (long)n * DIM_OUT + (long)n * NEXP;
    long zlo = (long)n * DIM_OUT, zhi = (long)out_size;
    if ((long)out_size >= need) {
        pout = out + ((long)out_size - (long)n * NEXP);
        zhi = (long)out_size - (long)n * NEXP;
    }

    moe_prep<<<256, 256>>>(W1, W2);
    moe_gate<<<1024, 256>>>(x, Wp, bp, Ee, out, zlo, zhi, pout, n);
    moe_build<<<1, 1>>>();
    moe_scatter<<<(n + 255) / 256, 256>>>(n);

    cudaFuncSetAttribute(moe_expert, cudaFuncAttributeMaxDynamicSharedMemorySize, SMEM_EXP);
    moe_expert<<<152, 256, SMEM_EXP>>>(b1, b2, out);
}

// round 12
// speedup vs baseline: 1.9013x; 1.0550x over previous
#include <cuda_runtime.h>
#include <cuda_fp16.h>
#include <mma.h>
#include <cstdint>

using namespace nvcuda;

#define DIM_IN  128
#define DIM_HID 256
#define DIM_OUT 128
#define NEXP    8
#define MAXN    65536
#define MAXROWS (2 * MAXN)
#define MAXTILES (MAXROWS / 128 + NEXP)

// ---------------- device scratch ----------------
__device__ int    g_counts[NEXP];
__device__ int    g_cursor[NEXP];
__device__ int    g_numTiles;
__device__ int    g_tileExpert[MAXTILES];
__device__ int    g_tileStart[MAXTILES];
__device__ int    g_tileRows[MAXTILES];
__device__ int    g_tokE[MAXN];
__device__ float2 g_tokW[MAXN];
__device__ int    g_rowToken[MAXROWS];
__device__ float  g_rowW[MAXROWS];

__device__ __align__(16) __half g_xf[MAXN * DIM_IN];
__device__ __align__(16) __half g_w1f[NEXP * DIM_IN * DIM_HID];  // [e][k=128][n=256]
__device__ __align__(16) __half g_w2f[NEXP * DIM_HID * DIM_OUT]; // [e][k=256][n=128]

__device__ __forceinline__ uint32_t packh2(float a, float b) {
    __half2 h = __floats2half2_rn(a, b);
    return *reinterpret_cast<uint32_t*>(&h);
}
__device__ __forceinline__ uint32_t smem_u32(const void* p) {
    uint32_t a;
    asm("{ .reg .u64 t; cvta.to.shared.u64 t, %1; cvt.u32.u64 %0, t; }" : "=r"(a) : "l"(p));
    return a;
}
#define CP_ASYNC16(dst, src) asm volatile("cp.async.cg.shared.global [%0], [%1], 16;" :: "r"(dst), "l"(src))
#define CP_COMMIT()          asm volatile("cp.async.commit_group;" ::: "memory")
#define CP_WAIT1()           asm volatile("cp.async.wait_group 1;" ::: "memory")

// ---------------- kernel: weight fp16 convert + zero counts ----------------
__global__ void __launch_bounds__(256) moe_prep(
    const float* __restrict__ W1, const float* __restrict__ W2)
{
    int idx = blockIdx.x * 256 + threadIdx.x;          // 0 .. 65535
    if (blockIdx.x == 0 && threadIdx.x < NEXP) g_counts[threadIdx.x] = 0;
    if (idx < 65536) {
        float4 v = reinterpret_cast<const float4*>(W1)[idx];
        reinterpret_cast<uint2*>(g_w1f)[idx] = make_uint2(packh2(v.x, v.y), packh2(v.z, v.w));
        float4 w = reinterpret_cast<const float4*>(W2)[idx];
        reinterpret_cast<uint2*>(g_w2f)[idx] = make_uint2(packh2(w.x, w.y), packh2(w.z, w.w));
    }
}

// ---------------- kernel: gate (+ X fp16 + output zeroing) ----------------
__global__ void __launch_bounds__(256) moe_gate(
    const float* __restrict__ x, const float* __restrict__ Wp,
    const float* __restrict__ bp, const float* __restrict__ Ee,
    float* __restrict__ outbuf, long zero_lo, long zero_hi,
    float* __restrict__ pout, int n)
{
    __shared__ float WpS[DIM_IN * 64];
    __shared__ float EeS[64 * NEXP];
    __shared__ float hS[8][64];
    __shared__ float pS[8][8];
    __shared__ int   cntS[NEXP];

    int tid = threadIdx.x, warp = tid >> 5, lane = tid & 31;
    for (int i = tid; i < DIM_IN * 64; i += 256) WpS[i] = Wp[i];
    for (int i = tid; i < 64 * NEXP; i += 256)   EeS[i] = Ee[i];
    if (tid < NEXP) cntS[tid] = 0;
    if (blockIdx.x == 0 && tid == 0) {
        for (long i = zero_lo; i < zero_hi; i++) outbuf[i] = 0.f;
    }
    __syncthreads();

    const float4 z4 = make_float4(0.f, 0.f, 0.f, 0.f);

    for (int tok = blockIdx.x * 8 + warp; tok < n; tok += gridDim.x * 8) {
        float xr[4];
        #pragma unroll
        for (int i = 0; i < 4; i++) xr[i] = x[(long)tok * DIM_IN + lane + 32 * i];

        reinterpret_cast<float4*>(outbuf + (long)tok * DIM_OUT)[lane] = z4;

        #pragma unroll
        for (int i = 0; i < 4; i++)
            g_xf[(long)tok * DIM_IN + lane + 32 * i] = __float2half_rn(xr[i]);

        float h0 = bp[lane], h1 = bp[lane + 32];
        #pragma unroll
        for (int d = 0; d < DIM_IN; d++) {
            float xd = __shfl_sync(0xffffffffu, xr[d >> 5], d & 31);
            h0 += xd * WpS[d * 64 + lane];
            h1 += xd * WpS[d * 64 + lane + 32];
        }
        hS[warp][lane] = h0;
        hS[warp][lane + 32] = h1;
        __syncwarp();

        if (lane < NEXP) {
            float lg = 0.f;
            #pragma unroll
            for (int e2 = 0; e2 < 64; e2++) lg += hS[warp][e2] * EeS[e2 * NEXP + lane];
            float p = 1.f / (1.f + expf(-lg * 0.2f));   // tau = 5
            pS[warp][lane] = p;
            if (pout) pout[(long)tok * NEXP + lane] = p;
        }
        __syncwarp();

        if (lane == 0) {
            float v0 = -1.f, v1 = -1.f; int i0 = 0, i1 = 0;
            #pragma unroll
            for (int j = 0; j < NEXP; j++) {
                float pv = pS[warp][j];
                if (pv > v0) { v1 = v0; i1 = i0; v0 = pv; i0 = j; }
                else if (pv > v1) { v1 = pv; i1 = j; }
            }
            float s = v0 + v1 + 1e-10f;
            g_tokE[tok] = i0 | (i1 << 8);
            g_tokW[tok] = make_float2(v0 / s, v1 / s);
            atomicAdd(&cntS[i0], 1);
            atomicAdd(&cntS[i1], 1);
        }
        __syncwarp();
    }
    __syncthreads();
    if (tid < NEXP) atomicAdd(&g_counts[tid], cntS[tid]);
}

// ---------------- kernel: scan + tile map ----------------
__global__ void moe_build() {
    if (threadIdx.x == 0) {
        int off = 0, tile = 0;
        for (int e = 0; e < NEXP; e++) {
            int c = g_counts[e];
            g_cursor[e] = off;
            for (int t = 0; t < c && tile < MAXTILES; t += 128) {
                g_tileExpert[tile] = e;
                g_tileStart[tile]  = off + t;
                g_tileRows[tile]   = min(128, c - t);
                tile++;
            }
            off += c;
        }
        g_numTiles = tile;
    }
}

// ---------------- kernel: scatter ----------------
__global__ void __launch_bounds__(256) moe_scatter(int n) {
    __shared__ int cnt[NEXP];
    __shared__ int base[NEXP];
    int tid = threadIdx.x;
    if (tid < NEXP) cnt[tid] = 0;
    __syncthreads();

    int tok = blockIdx.x * 256 + tid;
    int e0 = 0, e1 = 0, r0 = 0, r1 = 0; float2 w = make_float2(0.f, 0.f);
    bool ok = (tok < n);
    if (ok) {
        int e01 = g_tokE[tok];
        w = g_tokW[tok];
        e0 = e01 & 255; e1 = (e01 >> 8) & 255;
        r0 = atomicAdd(&cnt[e0], 1);
        r1 = atomicAdd(&cnt[e1], 1);
    }
    __syncthreads();
    if (tid < NEXP) base[tid] = atomicAdd(&g_cursor[tid], cnt[tid]);
    __syncthreads();
    if (ok) {
        int p0 = base[e0] + r0; g_rowToken[p0] = tok; g_rowW[p0] = w.x;
        int p1 = base[e1] + r1; g_rowToken[p1] = tok; g_rowW[p1] = w.y;
    }
}

// ---------------- kernel: persistent expert GEMM (fp16, 512 threads, 4x4 warp grid) ----------------
using FragA = wmma::fragment<wmma::matrix_a, 16, 16, 16, __half, wmma::row_major>;
using FragB = wmma::fragment<wmma::matrix_b, 16, 16, 16, __half, wmma::row_major>;
using FragC = wmma::fragment<wmma::accumulator, 16, 16, 16, float>;

#define LDX 136           // X / W2-chunk plane: 128 x 136 half
#define LDW 264           // W1 / H plane:       128 x 264 half
#define XB  (128 * LDX * 2)   // 34816 B
#define WB  (128 * LDW * 2)   // 67584 B
#define SMEM_EXP (2 * XB + 2 * WB)   // 204800 B
#define NTHR 512

__global__ void __launch_bounds__(NTHR, 1) moe_expert(
    const float* __restrict__ b1, const float* __restrict__ b2,
    float* __restrict__ out)
{
    extern __shared__ __align__(16) unsigned char sm[];
    __shared__ int   tokS[2][128];
    __shared__ float wS[2][128];
    __shared__ float b1s[256];
    __shared__ float b2s[128];

    int tid = threadIdx.x, warp = tid >> 5;
    int wm = warp >> 2, wn = warp & 3;    // 4x4 warp grid
    int m0 = wm * 32;
    int numTiles = g_numTiles;
    int stride = gridDim.x;
    uint32_t smb = smem_u32(sm);
    const uint4* x4g = (const uint4*)g_xf;

    // ---- prologue: prefetch first tile into buffer 0 ----
    int t0 = blockIdx.x;
    if (t0 < numTiles && tid < 128) {
        int rs = g_tileStart[t0], nr = g_tileRows[t0];
        int tok = -1; float w = 0.f;
        if (tid < nr) { tok = g_rowToken[rs + tid]; w = g_rowW[rs + tid]; }
        tokS[0][tid] = tok; wS[0][tid] = w;
    }
    __syncthreads();
    if (t0 < numTiles) {
        int e0 = g_tileExpert[t0];
        uint32_t xb = smb;
        for (int i = tid; i < 128 * 16; i += NTHR) {
            int r = i >> 4, u = i & 15;
            int tok = tokS[0][r]; if (tok < 0) tok = 0;
            CP_ASYNC16(xb + (uint32_t)(r * LDX + u * 8) * 2, x4g + (long)tok * 16 + u);
        }
        uint32_t wb = smb + 2 * XB;
        const uint4* w14 = (const uint4*)(g_w1f + (long)e0 * DIM_IN * DIM_HID);
        for (int i = tid; i < 128 * 32; i += NTHR) {
            int r = i >> 5, u = i & 31;
            CP_ASYNC16(wb + (uint32_t)(r * LDW + u * 8) * 2, w14 + i);
        }
    }
    CP_COMMIT();

    int buf = 0;
    for (int t = t0; t < numTiles; t += stride, buf ^= 1) {
        int e = g_tileExpert[t];
        int ntile = t + stride;
        int nb = buf ^ 1;

        __syncthreads();   // previous epilogue complete
        if (tid < 256) b1s[tid] = b1[(long)e * DIM_HID + tid];
        if (tid >= 256 && tid < 384) b2s[tid - 256] = b2[(long)e * DIM_OUT + tid - 256];
        if (ntile < numTiles && tid < 128) {
            int rs = g_tileStart[ntile], nr = g_tileRows[ntile];
            int tok = -1; float w = 0.f;
            if (tid < nr) { tok = g_rowToken[rs + tid]; w = g_rowW[rs + tid]; }
            tokS[nb][tid] = tok; wS[nb][tid] = w;
        }
        __syncthreads();

        // ---- issue next tile's prefetch ----
        if (ntile < numTiles) {
            int en = g_tileExpert[ntile];
            uint32_t xb = smb + (uint32_t)nb * XB;
            for (int i = tid; i < 128 * 16; i += NTHR) {
                int r = i >> 4, u = i & 15;
                int tok = tokS[nb][r]; if (tok < 0) tok = 0;
                CP_ASYNC16(xb + (uint32_t)(r * LDX + u * 8) * 2, x4g + (long)tok * 16 + u);
            }
            uint32_t wb = smb + 2 * XB + (uint32_t)nb * WB;
            const uint4* w14 = (const uint4*)(g_w1f + (long)en * DIM_IN * DIM_HID);
            for (int i = tid; i < 128 * 32; i += NTHR) {
                int r = i >> 5, u = i & 31;
                CP_ASYNC16(wb + (uint32_t)(r * LDW + u * 8) * 2, w14 + i);
            }
        }
        CP_COMMIT();
        CP_WAIT1();
        __syncthreads();

        __half* xr = (__half*)(sm + (size_t)buf * XB);
        __half* hw = (__half*)(sm + 2 * XB + (size_t)buf * WB);

        // ---- GEMM1: Hraw[128x256] = X @ W1 ; warp tile 32 x 64 ----
        FragC acc[2][4];
        #pragma unroll
        for (int mi = 0; mi < 2; mi++)
            #pragma unroll
            for (int nt = 0; nt < 4; nt++) wmma::fill_fragment(acc[mi][nt], 0.f);

        int nbase = wn * 64;
        #pragma unroll
        for (int ks = 0; ks < 8; ks++) {
            FragA a[2];
            #pragma unroll
            for (int mi = 0; mi < 2; mi++)
                wmma::load_matrix_sync(a[mi], &xr[(m0 + mi * 16) * LDX + ks * 16], LDX);
            #pragma unroll
            for (int nt = 0; nt < 4; nt++) {
                FragB b;
                wmma::load_matrix_sync(b, &hw[(ks * 16) * LDW + nbase + nt * 16], LDW);
                #pragma unroll
                for (int mi = 0; mi < 2; mi++)
                    wmma::mma_sync(acc[mi][nt], a[mi], b, acc[mi][nt]);
            }
        }
        // NOTE: warp wn's acc covers columns [wn*64, wn*64+64) — but H has 256 cols;
        // warps with wn cover n = wn*64 .. only 4*64 = 256. Correct: full coverage.
        __syncthreads();   // X and W1 fully consumed

        // ---- H = relu(acc + b1): 4 phases of 64 cols through dead X region ----
        float* stage = (float*)xr;   // 128 x 68 fp32 = 34816 B
        #pragma unroll
        for (int p = 0; p < 4; p++) {
            if (wn == p) {
                #pragma unroll
                for (int mi = 0; mi < 2; mi++)
                    #pragma unroll
                    for (int j = 0; j < 4; j++)
                        wmma::store_matrix_sync(&stage[(m0 + mi * 16) * 68 + j * 16],
                                                acc[mi][j], 68, wmma::mem_row_major);
            }
            __syncthreads();
            #pragma unroll 4
            for (int i = tid; i < 128 * 64; i += NTHR) {
                int r = i >> 6, c = i & 63;
                float v = stage[r * 68 + c] + b1s[p * 64 + c];
                v = v > 0.f ? v : 0.f;
                hw[r * LDW + p * 64 + c] = __float2half_rn(v);
            }
            __syncthreads();
        }

        // ---- GEMM2: C[128x128] = H @ W2, two K-chunks through dead X region ----
        FragC acc2[2][2];
        #pragma unroll
        for (int mi = 0; mi < 2; mi++)
            #pragma unroll
            for (int nt = 0; nt < 2; nt++) wmma::fill_fragment(acc2[mi][nt], 0.f);

        const uint4* w24 = (const uint4*)(g_w2f + (long)e * DIM_HID * DIM_OUT);
        #pragma unroll
        for (int ch = 0; ch < 2; ch++) {
            for (int i = tid; i < 128 * 16; i += NTHR) {
                int r = i >> 4, u = i & 15;
                *reinterpret_cast<uint4*>(&xr[r * LDX + u * 8]) = w24[(ch * 128 + r) * 16 + u];
            }
            __syncthreads();
            #pragma unroll
            for (int ks = 0; ks < 8; ks++) {
                FragA a[2];
                #pragma unroll
                for (int mi = 0; mi < 2; mi++)
                    wmma::load_matrix_sync(a[mi], &hw[(m0 + mi * 16) * LDW + ch * 128 + ks * 16], LDW);
                #pragma unroll
                for (int nt = 0; nt < 2; nt++) {
                    FragB b;
                    wmma::load_matrix_sync(b, &xr[(ks * 16) * LDX + wn * 32 + nt * 16], LDX);
                    #pragma unroll
                    for (int mi = 0; mi < 2; mi++)
                        wmma::mma_sync(acc2[mi][nt], a[mi], b, acc2[mi][nt]);
                }
            }
            __syncthreads();
        }

        // ---- epilogue: stage C (over dead H) then weighted atomics ----
        float* stC = (float*)hw;   // 128 x 132 fp32 = 67584 B
        #pragma unroll
        for (int mi = 0; mi < 2; mi++)
            #pragma unroll
            for (int nt = 0; nt < 2; nt++)
                wmma::store_matrix_sync(&stC[(m0 + mi * 16) * 132 + wn * 32 + nt * 16],
                                        acc2[mi][nt], 132, wmma::mem_row_major);
        __syncthreads();

        #pragma unroll 2
        for (int i = tid; i < 128 * DIM_OUT; i += NTHR) {
            int r = i >> 7, c = i & 127;
            int tok = tokS[buf][r];
            if (tok >= 0)
                atomicAdd(&out[(long)tok * DIM_OUT + c],
                          wS[buf][r] * (stC[r * 132 + c] + b2s[c]));
        }
    }
}

// ---------------- launch ----------------
extern "C" void kernel_launch(void* const* d_in, const int* in_sizes, int n_in,
                              void* d_out, int out_size) {
    const float* x  = (const float*)d_in[0];
    const float* Wp = (const float*)d_in[1];
    const float* bp = (const float*)d_in[2];
    const float* Ee = (const float*)d_in[3];
    const float* W1 = (const float*)d_in[4];
    const float* b1 = (const float*)d_in[5];
    const float* W2 = (const float*)d_in[6];
    const float* b2 = (const float*)d_in[7];
    float* out = (float*)d_out;

    int n = in_sizes[0] / DIM_IN;

    float* pout = nullptr;
    long need = (long)n * DIM_OUT + (long)n * NEXP;
    long zlo = (long)n * DIM_OUT, zhi = (long)out_size;
    if ((long)out_size >= need) {
        pout = out + ((long)out_size - (long)n * NEXP);
        zhi = (long)out_size - (long)n * NEXP;
    }

    moe_prep<<<256, 256>>>(W1, W2);
    moe_gate<<<1024, 256>>>(x, Wp, bp, Ee, out, zlo, zhi, pout, n);
    moe_build<<<1, 1>>>();
    moe_scatter<<<(n + 255) / 256, 256>>>(n);

    cudaFuncSetAttribute(moe_expert, cudaFuncAttributeMaxDynamicSharedMemorySize, SMEM_EXP);
    moe_expert<<<152, NTHR, SMEM_EXP>>>(b1, b2, out);
}